// round 5
// baseline (speedup 1.0000x reference)
#include <cuda_runtime.h>

// ---------------- problem constants ----------------
#define NDST0 67584
#define NDST1 6144
#define NDST2 1024
#define NE0   1013760
#define NE1   61440
#define NE2   5120
#define FIN   128
#define FH    256
#define NCLS  47

// ---------------- device scratch (referenced ONLY from device code) ----------------
__device__ float4 g_agg0 [NDST0 * FIN / 4];   // mean-aggregated neighbors, layer 0
__device__ float4 g_h1   [NDST0 * FH  / 4];   // layer-0 output (feeds layer-1 self+neigh)
__device__ float4 g_agg1 [NDST1 * FH  / 4];
__device__ float4 g_h2   [NDST1 * FH  / 4];   // layer-1 output
__device__ float4 g_agg2 [NDST2 * FH  / 4];
__device__ int    g_deg  [NDST0];
__device__ int    g_cur  [NDST0];
__device__ int    g_off  [NDST0 + 1];
__device__ int    g_esrc [NE0];               // CSR-ordered source row ids

// ---------------- tiny utility kernels ----------------
__global__ void zero2_kernel(int n)
{
    int i = blockIdx.x * blockDim.x + threadIdx.x;
    if (i < n) { g_deg[i] = 0; g_cur[i] = 0; }
}

__global__ void hist_kernel(const int* __restrict__ dst, int E)
{
    int e = blockIdx.x * blockDim.x + threadIdx.x;
    if (e < E) atomicAdd(&g_deg[dst[e]], 1);
}

// single-block exclusive scan over g_deg -> g_off (shfl-based, 2 barriers per tile)
__global__ void scan_kernel(int n)
{
    __shared__ int warpsum[32];
    __shared__ int s_carry;
    const int tid  = threadIdx.x;
    const int lane = tid & 31;
    const int wid  = tid >> 5;
    if (tid == 0) s_carry = 0;
    __syncthreads();
    for (int base = 0; base < n; base += 1024) {
        int idx = base + tid;
        int v = (idx < n) ? g_deg[idx] : 0;
        // inclusive scan within warp
        int x = v;
#pragma unroll
        for (int st = 1; st < 32; st <<= 1) {
            int t = __shfl_up_sync(0xFFFFFFFFu, x, st);
            if (lane >= st) x += t;
        }
        if (lane == 31) warpsum[wid] = x;
        __syncthreads();
        if (wid == 0) {
            int w = warpsum[lane];
#pragma unroll
            for (int st = 1; st < 32; st <<= 1) {
                int t = __shfl_up_sync(0xFFFFFFFFu, w, st);
                if (lane >= st) w += t;
            }
            warpsum[lane] = w;   // inclusive warp totals
        }
        __syncthreads();
        int woff  = (wid > 0) ? warpsum[wid - 1] : 0;
        int carry = s_carry;
        if (idx < n) g_off[idx] = carry + woff + x - v;   // exclusive
        __syncthreads();                                   // all reads of s_carry/warpsum done
        if (tid == 0) s_carry = carry + warpsum[31];
        __syncthreads();
    }
    if (threadIdx.x == 0) g_off[n] = s_carry;
}

// CSR scatter; REMAP=1 resolves the emb-table indirection (layer 0)
template <int REMAP>
__global__ void scatter_kernel(const int* __restrict__ src, const int* __restrict__ dst, int E,
                               const int* __restrict__ remap)
{
    int e = blockIdx.x * blockDim.x + threadIdx.x;
    if (e >= E) return;
    int d = dst[e];
    int p = g_off[d] + atomicAdd(&g_cur[d], 1);
    int s = src[e];
    g_esrc[p] = REMAP ? remap[s] : s;
}

// ---------------- mean aggregation: one warp per destination ----------------
// LAYER 0: src rows from emb (arg), F=128, dst = g_agg0
// LAYER 1: src rows from g_h1,  F=256, dst = g_agg1
// LAYER 2: src rows from g_h2,  F=256, dst = g_agg2
template <int LAYER>
__global__ void agg_kernel(const float4* __restrict__ hExt, int n_dst)
{
    const float4* __restrict__ h4 =
        (LAYER == 0) ? hExt : (LAYER == 1) ? (const float4*)g_h1 : (const float4*)g_h2;
    float4* __restrict__ agg4 =
        (LAYER == 0) ? g_agg0 : (LAYER == 1) ? g_agg1 : g_agg2;
    const int VPL = (LAYER == 0) ? 1 : 2;
    const int F4  = VPL * 32;

    int w = (blockIdx.x * blockDim.x + threadIdx.x) >> 5;
    int lane = threadIdx.x & 31;
    if (w >= n_dst) return;
    int s = g_off[w], e = g_off[w + 1];

    float4 acc[VPL];
#pragma unroll
    for (int v = 0; v < VPL; v++) acc[v] = make_float4(0.f, 0.f, 0.f, 0.f);

    int i = s;
    for (; i + 1 < e; i += 2) {           // unroll x2 for MLP
        int r0 = g_esrc[i], r1 = g_esrc[i + 1];
#pragma unroll
        for (int v = 0; v < VPL; v++) {
            float4 x = h4[(size_t)r0 * F4 + v * 32 + lane];
            float4 y = h4[(size_t)r1 * F4 + v * 32 + lane];
            acc[v].x += x.x + y.x; acc[v].y += x.y + y.y;
            acc[v].z += x.z + y.z; acc[v].w += x.w + y.w;
        }
    }
    if (i < e) {
        int r0 = g_esrc[i];
#pragma unroll
        for (int v = 0; v < VPL; v++) {
            float4 x = h4[(size_t)r0 * F4 + v * 32 + lane];
            acc[v].x += x.x; acc[v].y += x.y; acc[v].z += x.z; acc[v].w += x.w;
        }
    }
    int cnt = e - s;
    float inv = 1.0f / (float)(cnt > 0 ? cnt : 1);
#pragma unroll
    for (int v = 0; v < VPL; v++) {
        agg4[(size_t)w * F4 + v * 32 + lane] =
            make_float4(acc[v].x * inv, acc[v].y * inv, acc[v].z * inv, acc[v].w * inv);
    }
}

// ---------------- dual-operand SGEMM ----------------
// C = relu( A1@B1 + A2@B2 + bias )
// LAYER 0: A1 = emb with row remap via input_nodes, A2 = g_agg0, C = g_h1, K=FIN
// LAYER 1: A1 = g_h1,                               A2 = g_agg1, C = g_h2, K=FH
// BM=BN=128, BK=8, 256 threads, 8x8 per thread
template <int LAYER>
__global__ void __launch_bounds__(256, 2) gemm2_kernel(
    const float* __restrict__ A1ext,         // emb (layer 0); unused layer 1
    const int*   __restrict__ inodes,        // input_nodes (layer 0); unused layer 1
    const float* __restrict__ B1, const float* __restrict__ B2,
    const float* __restrict__ bias)
{
    const float* __restrict__ A1 =
        (LAYER == 0) ? A1ext : (const float*)g_h1;
    const float* __restrict__ A2 =
        (LAYER == 0) ? (const float*)g_agg0 : (const float*)g_agg1;
    float* __restrict__ C = (LAYER == 0) ? (float*)g_h1 : (float*)g_h2;
    const int K = (LAYER == 0) ? FIN : FH;
    const int N = FH;

    __shared__ float As[8][128];   // transposed A tile (k-major)
    __shared__ float Bs[8][128];
    const int tid = threadIdx.x;
    const int tx = tid & 15;       // N direction (16)
    const int ty = tid >> 4;       // M direction (16)
    const int bx = blockIdx.x;
    const int by = blockIdx.y;

    const int aRow = tid >> 1;             // 0..127
    const int aCol = (tid & 1) << 2;       // 0 or 4
    const int bRow = tid >> 5;             // 0..7
    const int bCol = (tid & 31) << 2;      // 0..124

    const int am   = by * 128 + aRow;                       // logical A row
    const int amA1 = (LAYER == 0) ? __ldg(&inodes[am]) : am; // physical row for A1 phase

    float acc[8][8];
#pragma unroll
    for (int i = 0; i < 8; i++)
#pragma unroll
        for (int j = 0; j < 8; j++) acc[i][j] = 0.f;

    const int KT = K >> 3;
    for (int t = 0; t < 2 * KT; t++) {
        const bool ph1 = (t < KT);
        const float* A = ph1 ? A1 : A2;
        const float* B = ph1 ? B1 : B2;
        const int arow = ph1 ? amA1 : am;
        const int k0 = (ph1 ? t : t - KT) << 3;

        float4 av = *(const float4*)(A + (size_t)arow * K + k0 + aCol);
        float4 bv = *(const float4*)(B + (size_t)(k0 + bRow) * N + bx * 128 + bCol);
        As[aCol + 0][aRow] = av.x; As[aCol + 1][aRow] = av.y;
        As[aCol + 2][aRow] = av.z; As[aCol + 3][aRow] = av.w;
        *(float4*)&Bs[bRow][bCol] = bv;
        __syncthreads();

#pragma unroll
        for (int k = 0; k < 8; k++) {
            float4 a0 = *(const float4*)&As[k][ty * 4];
            float4 a1 = *(const float4*)&As[k][64 + ty * 4];
            float4 b0 = *(const float4*)&Bs[k][tx * 4];
            float4 b1 = *(const float4*)&Bs[k][64 + tx * 4];
            float af[8] = {a0.x, a0.y, a0.z, a0.w, a1.x, a1.y, a1.z, a1.w};
            float bf[8] = {b0.x, b0.y, b0.z, b0.w, b1.x, b1.y, b1.z, b1.w};
#pragma unroll
            for (int i = 0; i < 8; i++)
#pragma unroll
                for (int j = 0; j < 8; j++) acc[i][j] += af[i] * bf[j];
        }
        __syncthreads();
    }

    const int c0 = bx * 128 + tx * 4;
    const int c1 = bx * 128 + 64 + tx * 4;
    float4 bias0 = *(const float4*)(bias + c0);
    float4 bias1 = *(const float4*)(bias + c1);
#pragma unroll
    for (int i = 0; i < 8; i++) {
        int r = by * 128 + ((i < 4) ? (ty * 4 + i) : (64 + ty * 4 + i - 4));
        float4 v0 = make_float4(acc[i][0] + bias0.x, acc[i][1] + bias0.y,
                                acc[i][2] + bias0.z, acc[i][3] + bias0.w);
        float4 v1 = make_float4(acc[i][4] + bias1.x, acc[i][5] + bias1.y,
                                acc[i][6] + bias1.z, acc[i][7] + bias1.w);
        v0.x = fmaxf(v0.x, 0.f); v0.y = fmaxf(v0.y, 0.f);
        v0.z = fmaxf(v0.z, 0.f); v0.w = fmaxf(v0.w, 0.f);
        v1.x = fmaxf(v1.x, 0.f); v1.y = fmaxf(v1.y, 0.f);
        v1.z = fmaxf(v1.z, 0.f); v1.w = fmaxf(v1.w, 0.f);
        *(float4*)(C + (size_t)r * N + c0) = v0;
        *(float4*)(C + (size_t)r * N + c1) = v1;
    }
}

// ---------------- layer 2 (tiny, N=47) ----------------
__global__ void layer2_kernel(const float* __restrict__ Ws, const float* __restrict__ Wn,
                              const float* __restrict__ b, float* __restrict__ out)
{
    int m = blockIdx.x;
    int n = threadIdx.x;
    if (n >= NCLS) return;
    float acc = b[n];
    const float* hr = (const float*)g_h2   + (size_t)m * FH;
    const float* ar = (const float*)g_agg2 + (size_t)m * FH;
#pragma unroll 4
    for (int k = 0; k < FH; k++)
        acc += hr[k] * Ws[k * NCLS + n] + ar[k] * Wn[k * NCLS + n];
    out[m * NCLS + n] = acc;
}

// ---------------- orchestration (kernel launches ONLY — graph-capturable) ----------------
extern "C" void kernel_launch(void* const* d_in, const int* in_sizes, int n_in,
                              void* d_out, int out_size)
{
    (void)in_sizes; (void)n_in; (void)out_size;
    // metadata.txt order == setup_inputs() insertion order:
    // emb_table, input_nodes, src0, dst0, src1, dst1, src2, dst2,
    // Wself0, Wneigh0, b0, Wself1, Wneigh1, b1, Wself2, Wneigh2, b2
    const float* emb         = (const float*)d_in[0];
    const int*   input_nodes = (const int*)  d_in[1];
    const int*   src0        = (const int*)  d_in[2];
    const int*   dst0        = (const int*)  d_in[3];
    const int*   src1        = (const int*)  d_in[4];
    const int*   dst1        = (const int*)  d_in[5];
    const int*   src2        = (const int*)  d_in[6];
    const int*   dst2        = (const int*)  d_in[7];
    const float* Ws0         = (const float*)d_in[8];
    const float* Wn0         = (const float*)d_in[9];
    const float* b0          = (const float*)d_in[10];
    const float* Ws1         = (const float*)d_in[11];
    const float* Wn1         = (const float*)d_in[12];
    const float* b1          = (const float*)d_in[13];
    const float* Ws2         = (const float*)d_in[14];
    const float* Wn2         = (const float*)d_in[15];
    const float* b2          = (const float*)d_in[16];
    float* out = (float*)d_out;

    const int TB = 256;

    // ---- layer 0 ----
    zero2_kernel<<<(NDST0 + TB - 1) / TB, TB>>>(NDST0);
    hist_kernel<<<(NE0 + TB - 1) / TB, TB>>>(dst0, NE0);
    scan_kernel<<<1, 1024>>>(NDST0);
    scatter_kernel<1><<<(NE0 + TB - 1) / TB, TB>>>(src0, dst0, NE0, input_nodes);
    agg_kernel<0><<<(NDST0 + 7) / 8, TB>>>((const float4*)emb, NDST0);
    {
        dim3 grid(FH / 128, NDST0 / 128);
        gemm2_kernel<0><<<grid, 256>>>(emb, input_nodes, Ws0, Wn0, b0);
    }

    // ---- layer 1 ----
    zero2_kernel<<<(NDST1 + TB - 1) / TB, TB>>>(NDST1);
    hist_kernel<<<(NE1 + TB - 1) / TB, TB>>>(dst1, NE1);
    scan_kernel<<<1, 1024>>>(NDST1);
    scatter_kernel<0><<<(NE1 + TB - 1) / TB, TB>>>(src1, dst1, NE1, input_nodes);
    agg_kernel<1><<<(NDST1 + 7) / 8, TB>>>((const float4*)emb, NDST1);
    {
        dim3 grid(FH / 128, NDST1 / 128);
        gemm2_kernel<1><<<grid, 256>>>(emb, input_nodes, Ws1, Wn1, b1);
    }

    // ---- layer 2 ----
    zero2_kernel<<<(NDST2 + TB - 1) / TB, TB>>>(NDST2);
    hist_kernel<<<(NE2 + TB - 1) / TB, TB>>>(dst2, NE2);
    scan_kernel<<<1, 1024>>>(NDST2);
    scatter_kernel<0><<<(NE2 + TB - 1) / TB, TB>>>(src2, dst2, NE2, input_nodes);
    agg_kernel<2><<<(NDST2 + 7) / 8, TB>>>((const float4*)emb, NDST2);
    layer2_kernel<<<NDST2, 64>>>(Ws2, Wn2, b2, out);
}